// round 15
// baseline (speedup 1.0000x reference)
#include <cuda_runtime.h>
#include <cuda_bf16.h>
#include <math.h>
#include <stdint.h>

#define BN 131072
#define DD 256
#define NBLK (BN / 64)

// ---------------- scratch (device globals: allocation-free) ----------------
__device__ __align__(16) short       g_hs1[(size_t)BN * DD];   // layer0 out (int16, exact)
__device__ __align__(16) short       g_hs2[(size_t)BN * DD];   // layer1 out
__device__ float                     g_mu[3][BN];
__device__ float                     g_rstd[3][BN];
__device__ unsigned                  g_gamma[3];
__device__ float                     g_beta[3];
__device__ __align__(16) signed char g_wb[3][DD * DD];         // +-1 int8, swizzled [n][k] layout

__device__ __forceinline__ uint32_t smem_u32(const void* p) {
    uint32_t a;
    asm("{ .reg .u64 t; cvta.to.shared.u64 t, %1; cvt.u32.u64 %0, t; }" : "=r"(a) : "l"(p));
    return a;
}

#define MBAR_INIT(mb, c) asm volatile("mbarrier.init.shared.b64 [%0], %1;" :: "r"(mb), "r"(c) : "memory")

#define MBAR_WAIT(mbar_smem_addr, phase_parity) do {                                         \
    uint32_t _mbar = (uint32_t)(mbar_smem_addr);                                             \
    uint32_t _parity = (uint32_t)(phase_parity);                                             \
    uint32_t _done;                                                                          \
    asm volatile(                                                                            \
        "{\n\t.reg .pred p;\n\t"                                                             \
        "mbarrier.try_wait.parity.shared.b64 p, [%1], %2;\n\t"                               \
        "selp.b32 %0, 1, 0, p;\n\t}"                                                         \
        : "=r"(_done) : "r"(_mbar), "r"(_parity) : "memory");                                \
    if (!_done) {                                                                            \
        asm volatile(                                                                        \
            "{\n\t.reg .pred P1;\n\t"                                                        \
            "WAIT_LOOP_%=:\n\t"                                                              \
            "mbarrier.try_wait.parity.shared.b64 P1, [%0], %1;\n\t"                          \
            "@P1 bra.uni WAIT_DONE_%=;\n\t"                                                  \
            "bra.uni WAIT_LOOP_%=;\n\t"                                                      \
            "WAIT_DONE_%=:\n\t}"                                                             \
            :: "r"(_mbar), "r"(_parity) : "memory");                                         \
    }                                                                                        \
} while (0)

__device__ __forceinline__ unsigned qpack4f(float4 f, float sc, float bi) {
    int q0 = __float2int_rn(fminf(fmaxf(fmaf(f.x, sc, bi), -127.f), 127.f));
    int q1 = __float2int_rn(fminf(fmaxf(fmaf(f.y, sc, bi), -127.f), 127.f));
    int q2 = __float2int_rn(fminf(fmaxf(fmaf(f.z, sc, bi), -127.f), 127.f));
    int q3 = __float2int_rn(fminf(fmaxf(fmaf(f.w, sc, bi), -127.f), 127.f));
    return ((unsigned)q0 & 0xFFu) | (((unsigned)q1 & 0xFFu) << 8) |
           (((unsigned)q2 & 0xFFu) << 16) | (((unsigned)q3 & 0xFFu) << 24);
}

// pack 8 int16 (from one uint4) -> 2 quantized u32
__device__ __forceinline__ void qpack_s16(uint4 u, float sc, float bi, unsigned& w0, unsigned& w1) {
    unsigned uu[4] = {u.x, u.y, u.z, u.w};
    unsigned w[2];
#pragma unroll
    for (int h = 0; h < 2; ++h) {
        unsigned r = 0;
#pragma unroll
        for (int b = 0; b < 2; ++b) {
            unsigned raw = uu[h * 2 + b];
            float t0 = fminf(fmaxf(fmaf((float)(short)(raw & 0xFFFF), sc, bi), -127.f), 127.f);
            float t1 = fminf(fmaxf(fmaf((float)(short)(raw >> 16),    sc, bi), -127.f), 127.f);
            r |= ((unsigned)__float2int_rn(t0) & 0xFFu) << (16 * b);
            r |= ((unsigned)__float2int_rn(t1) & 0xFFu) << (16 * b + 8);
        }
        w[h] = r;
    }
    w0 = w[0]; w1 = w[1];
}

// ---------------- init ----------------
__global__ void init_kernel() {
    if (threadIdx.x < 3) g_gamma[threadIdx.x] = 0u;
}

// ---------------- weight prep: alpha/beta + sign -> swizzled int8 ---------
__global__ void __launch_bounds__(1024) wprep_kernel(const float* __restrict__ W1,
                                                     const float* __restrict__ W2,
                                                     const float* __restrict__ W3) {
    const float* W = blockIdx.x == 0 ? W1 : (blockIdx.x == 1 ? W2 : W3);
    __shared__ float ps[32], pa[32];
    __shared__ float s_alpha;
    int tid = threadIdx.x;
    float s = 0.f, sa = 0.f;
    for (int i = tid; i < DD * DD; i += 1024) {
        float w = W[i];
        s += w; sa += fabsf(w);
    }
#pragma unroll
    for (int o = 16; o; o >>= 1) {
        s  += __shfl_xor_sync(0xffffffffu, s,  o);
        sa += __shfl_xor_sync(0xffffffffu, sa, o);
    }
    if ((tid & 31) == 0) { ps[tid >> 5] = s; pa[tid >> 5] = sa; }
    __syncthreads();
    if (tid == 0) {
        float ts = 0.f, ta = 0.f;
        for (int i = 0; i < 32; i++) { ts += ps[i]; ta += pa[i]; }  // fixed order
        float alpha = ts / 65536.0f;
        g_beta[blockIdx.x] = fmaxf(ta / 65536.0f, 1e-8f);
        s_alpha = alpha;
    }
    __syncthreads();
    float alpha = s_alpha;
    signed char* wb = g_wb[blockIdx.x];
    for (int i = tid; i < DD * DD; i += 1024) {
        int n = i >> 8, k = i & 255;
        signed char v = ((W[i] - alpha) > 0.f) ? (signed char)1 : (signed char)-1;
        unsigned off = (unsigned)n * 256u + ((((unsigned)k >> 4) ^ ((unsigned)n & 7u)) << 4) + ((unsigned)k & 15u);
        wb[off] = v;
    }
}

// ---------------- stats for x: 2 rows/warp (MLP=4) ------------------------
__global__ void __launch_bounds__(256) stats_kernel(const float* __restrict__ x) {
    __shared__ unsigned sg;
    int tid = threadIdx.x;
    if (tid == 0) sg = 0u;
    __syncthreads();
    int warp = tid >> 5, lane = tid & 31;
    size_t row = (size_t)blockIdx.x * 16 + warp * 2;
    const float* xr0 = x + row * DD;
    const float* xr1 = xr0 + DD;
    float4 a0 = *(const float4*)(xr0 + lane * 4);
    float4 a1 = *(const float4*)(xr1 + lane * 4);
    float4 b0 = *(const float4*)(xr0 + 128 + lane * 4);
    float4 b1 = *(const float4*)(xr1 + 128 + lane * 4);
    float s0 = ((a0.x + a0.y) + (a0.z + a0.w)) + ((b0.x + b0.y) + (b0.z + b0.w));
    float s1 = ((a1.x + a1.y) + (a1.z + a1.w)) + ((b1.x + b1.y) + (b1.z + b1.w));
#pragma unroll
    for (int o = 16; o; o >>= 1) {
        s0 += __shfl_xor_sync(0xffffffffu, s0, o);
        s1 += __shfl_xor_sync(0xffffffffu, s1, o);
    }
    float mu0 = s0 * (1.0f / 256.0f);
    float mu1 = s1 * (1.0f / 256.0f);
    float ss0 = 0.f, mx0 = 0.f, ss1 = 0.f, mx1 = 0.f, d;
    d = a0.x - mu0; ss0 += d * d; mx0 = fmaxf(mx0, fabsf(d));
    d = a0.y - mu0; ss0 += d * d; mx0 = fmaxf(mx0, fabsf(d));
    d = a0.z - mu0; ss0 += d * d; mx0 = fmaxf(mx0, fabsf(d));
    d = a0.w - mu0; ss0 += d * d; mx0 = fmaxf(mx0, fabsf(d));
    d = b0.x - mu0; ss0 += d * d; mx0 = fmaxf(mx0, fabsf(d));
    d = b0.y - mu0; ss0 += d * d; mx0 = fmaxf(mx0, fabsf(d));
    d = b0.z - mu0; ss0 += d * d; mx0 = fmaxf(mx0, fabsf(d));
    d = b0.w - mu0; ss0 += d * d; mx0 = fmaxf(mx0, fabsf(d));
    d = a1.x - mu1; ss1 += d * d; mx1 = fmaxf(mx1, fabsf(d));
    d = a1.y - mu1; ss1 += d * d; mx1 = fmaxf(mx1, fabsf(d));
    d = a1.z - mu1; ss1 += d * d; mx1 = fmaxf(mx1, fabsf(d));
    d = a1.w - mu1; ss1 += d * d; mx1 = fmaxf(mx1, fabsf(d));
    d = b1.x - mu1; ss1 += d * d; mx1 = fmaxf(mx1, fabsf(d));
    d = b1.y - mu1; ss1 += d * d; mx1 = fmaxf(mx1, fabsf(d));
    d = b1.z - mu1; ss1 += d * d; mx1 = fmaxf(mx1, fabsf(d));
    d = b1.w - mu1; ss1 += d * d; mx1 = fmaxf(mx1, fabsf(d));
#pragma unroll
    for (int o = 16; o; o >>= 1) {
        ss0 += __shfl_xor_sync(0xffffffffu, ss0, o);
        ss1 += __shfl_xor_sync(0xffffffffu, ss1, o);
        mx0  = fmaxf(mx0, __shfl_xor_sync(0xffffffffu, mx0, o));
        mx1  = fmaxf(mx1, __shfl_xor_sync(0xffffffffu, mx1, o));
    }
    float rsd0 = 1.0f / sqrtf(ss0 * (1.0f / 256.0f) + 1e-5f);
    float rsd1 = 1.0f / sqrtf(ss1 * (1.0f / 256.0f) + 1e-5f);
    if (lane == 0) {
        g_mu[0][row]       = mu0;
        g_mu[0][row + 1]   = mu1;
        g_rstd[0][row]     = rsd0;
        g_rstd[0][row + 1] = rsd1;
        atomicMax(&sg, __float_as_uint(fmaxf(mx0 * rsd0, mx1 * rsd1)));
    }
    __syncthreads();
    if (tid == 0) atomicMax(&g_gamma[0], sg);
}

// ---------------- fused layer: pipelined LN+quant -> IMMA -> epilogue -----
// CTA: 64 rows x 256 cols, K=256. 256 threads = 8 warps (2M x 4N), warp 32x64.
// Fill k<128 half -> prefetch k>=128 -> MMA kk0..3 (loads in flight) ->
// store k>=128 half -> MMA kk4..7. B via cp.async.bulk. 2 CTAs / SM.
template <int L>
__global__ void __launch_bounds__(256, 2) layer_kernel(const float* __restrict__ xin,
                                                       float* __restrict__ fout) {
    constexpr bool LAST = (L == 2);
    extern __shared__ char smem[];
    int*      risum = (int*)smem;                   // [4][64]
    float*    rsq   = (float*)(smem + 1024);        // [4][64]
    int*      rivx  = (int*)(smem + 2048);          // [4][64]
    int*      rivn  = (int*)(smem + 3072);          // [4][64]
    unsigned* sgmax = (unsigned*)(smem + 4096);
    char*     Asm   = smem + 4352;
    char*     Bsm   = smem + 20736;
    const uint32_t A_u  = smem_u32(Asm);
    const uint32_t B_u  = smem_u32(Bsm);
    const uint32_t MBAR = smem_u32(smem + 4104);

    const int tid = threadIdx.x;
    const int warp = tid >> 5, lane = tid & 31;
    const int row0 = blockIdx.x * 64;

    // ---- B: single-thread async bulk copy (overlaps the A-fill below) ----
    if (tid == 0) {
        *sgmax = 0u;
        MBAR_INIT(MBAR, 1);
        asm volatile("mbarrier.arrive.expect_tx.shared.b64 _, [%0], %1;"
                     :: "r"(MBAR), "r"(65536u) : "memory");
        asm volatile("cp.async.bulk.shared::cta.global.mbarrier::complete_tx::bytes "
                     "[%0], [%1], %2, [%3];"
                     :: "r"(B_u), "l"((const void*)g_wb[L]), "r"(65536u), "r"(MBAR)
                     : "memory");
    }

    const float gamma  = fmaxf(__uint_as_float(g_gamma[L]), 1e-8f);
    const float qs     = 127.0f / gamma;
    const float oscale = g_beta[L] * gamma / 127.0f;
    float poscale = 0.f;
    if (L > 0) poscale = g_beta[L - 1] * fmaxf(__uint_as_float(g_gamma[L - 1]), 1e-8f) / 127.0f;

    const short* sprev = (L == 1) ? g_hs1 : g_hs2;
    short* outs = (L == 0) ? g_hs1 : g_hs2;

    // ---- per-thread fill coords (row fixed; 4 ch-columns over iterations) --
    const int fr  = tid & 63;        // row within block
    const int fch = tid >> 6;        // 0..3
    const int fgrow = row0 + fr;
    float sc = g_rstd[L][fgrow] * qs;
    float bi = -g_mu[L][fgrow] * sc;
    const float scq = (L > 0) ? poscale * sc : sc;

    // ---- fill half0: ch = fch, 4+fch  (k < 128) ----
#pragma unroll
    for (int it = 0; it < 2; ++it) {
        int ch = it * 4 + fch;
        unsigned pk[4];
        if (L == 0) {
            const float* p = xin + (size_t)fgrow * DD + ch * 16;
            pk[0] = qpack4f(*(const float4*)(p),      scq, bi);
            pk[1] = qpack4f(*(const float4*)(p + 4),  scq, bi);
            pk[2] = qpack4f(*(const float4*)(p + 8),  scq, bi);
            pk[3] = qpack4f(*(const float4*)(p + 12), scq, bi);
        } else {
            const short* p = sprev + (size_t)fgrow * DD + ch * 16;
            qpack_s16(*(const uint4*)(p),     scq, bi, pk[0], pk[1]);
            qpack_s16(*(const uint4*)(p + 8), scq, bi, pk[2], pk[3]);
        }
        unsigned off = (unsigned)fr * 256u + ((((unsigned)ch) ^ ((unsigned)fr & 7u)) << 4);
        *(uint4*)(Asm + off) = make_uint4(pk[0], pk[1], pk[2], pk[3]);
    }

    // ---- prefetch half1 raw into registers (LDGs overlap MMA part 1) ----
    uint4 pf0, pf1, pf2, pf3;   // L0: ch 8+fch (4x16B); L>=1: ch 8+fch (2) + ch 12+fch (2)
    if (L == 0) {
        const float* p = xin + (size_t)fgrow * DD + (8 + fch) * 16;
        pf0 = *(const uint4*)(p);
        pf1 = *(const uint4*)(p + 4);
        pf2 = *(const uint4*)(p + 8);
        pf3 = *(const uint4*)(p + 12);
    } else {
        const short* p2 = sprev + (size_t)fgrow * DD + (8 + fch) * 16;
        const short* p3 = sprev + (size_t)fgrow * DD + (12 + fch) * 16;
        pf0 = *(const uint4*)(p2);
        pf1 = *(const uint4*)(p2 + 8);
        pf2 = *(const uint4*)(p3);
        pf3 = *(const uint4*)(p3 + 8);
    }

    __syncthreads();        // A half0 visible (and MBAR init to all threads)
    MBAR_WAIT(MBAR, 0);     // B bulk copy complete

    // ---- MMA setup: warp tile 32(M) x 64(N) ----
    const int wm = warp & 1;
    const int wn = warp >> 1;

    uint32_t a_base[2]; unsigned a_x7[2];
#pragma unroll
    for (int i = 0; i < 2; ++i) {
        int r = wm * 32 + i * 16 + (lane & 15);
        a_base[i] = A_u + (unsigned)r * 256u;
        a_x7[i] = (unsigned)r & 7u;
    }
    uint32_t b_base[4]; unsigned b_x7[4];
#pragma unroll
    for (int jp = 0; jp < 4; ++jp) {
        int n = wn * 64 + jp * 16 + ((lane >> 4) << 3) + (lane & 7);
        b_base[jp] = B_u + (unsigned)n * 256u;
        b_x7[jp] = (unsigned)n & 7u;
    }
    const unsigned a_ck = (unsigned)(lane >> 4);
    const unsigned b_ck = (unsigned)((lane >> 3) & 1);

    int acc[2][8][4];
#pragma unroll
    for (int i = 0; i < 2; i++)
#pragma unroll
        for (int j = 0; j < 8; j++)
#pragma unroll
            for (int r = 0; r < 4; r++) acc[i][j][r] = 0;

#define MMA_KSTEP(kk)                                                                        \
    {                                                                                        \
        unsigned a[2][4];                                                                    \
        _Pragma("unroll")                                                                    \
        for (int i = 0; i < 2; ++i) {                                                        \
            uint32_t ad = a_base[i] + ((((unsigned)((kk) * 2) + a_ck) ^ a_x7[i]) << 4);      \
            asm volatile("ldmatrix.sync.aligned.m8n8.x4.shared.b16 {%0,%1,%2,%3}, [%4];"     \
                         : "=r"(a[i][0]), "=r"(a[i][1]), "=r"(a[i][2]), "=r"(a[i][3])        \
                         : "r"(ad));                                                         \
        }                                                                                    \
        _Pragma("unroll")                                                                    \
        for (int jp = 0; jp < 4; ++jp) {                                                     \
            uint32_t bd = b_base[jp] + ((((unsigned)((kk) * 2) + b_ck) ^ b_x7[jp]) << 4);    \
            unsigned rb[4];                                                                  \
            asm volatile("ldmatrix.sync.aligned.m8n8.x4.shared.b16 {%0,%1,%2,%3}, [%4];"     \
                         : "=r"(rb[0]), "=r"(rb[1]), "=r"(rb[2]), "=r"(rb[3])                \
                         : "r"(bd));                                                         \
            _Pragma("unroll")                                                                \
            for (int i = 0; i < 2; ++i) {                                                    \
                asm volatile(                                                                \
                    "mma.sync.aligned.m16n8k32.row.col.s32.s8.s8.s32 "                       \
                    "{%0,%1,%2,%3}, {%4,%5,%6,%7}, {%8,%9}, {%0,%1,%2,%3};\n"                \
                    : "+r"(acc[i][2 * jp][0]), "+r"(acc[i][2 * jp][1]),                      \
                      "+r"(acc[i][2 * jp][2]), "+r"(acc[i][2 * jp][3])                       \
                    : "r"(a[i][0]), "r"(a[i][1]), "r"(a[i][2]), "r"(a[i][3]),                \
                      "r"(rb[0]), "r"(rb[1]));                                               \
                asm volatile(                                                                \
                    "mma.sync.aligned.m16n8k32.row.col.s32.s8.s8.s32 "                       \
                    "{%0,%1,%2,%3}, {%4,%5,%6,%7}, {%8,%9}, {%0,%1,%2,%3};\n"                \
                    : "+r"(acc[i][2 * jp + 1][0]), "+r"(acc[i][2 * jp + 1][1]),              \
                      "+r"(acc[i][2 * jp + 1][2]), "+r"(acc[i][2 * jp + 1][3])               \
                    : "r"(a[i][0]), "r"(a[i][1]), "r"(a[i][2]), "r"(a[i][3]),                \
                      "r"(rb[2]), "r"(rb[3]));                                               \
            }                                                                                \
        }                                                                                    \
    }

    // ---- MMA part 1: kk = 0..3 (half1 LDGs in flight) ----
#pragma unroll
    for (int kk = 0; kk < 4; ++kk) MMA_KSTEP(kk);

    // ---- finish half1: quantize prefetched regs, store to Asm ----
    if (L == 0) {
        const float* p3 = xin + (size_t)fgrow * DD + (12 + fch) * 16;
        uint4 g0 = *(const uint4*)(p3);
        uint4 g1 = *(const uint4*)(p3 + 4);
        uint4 g2 = *(const uint4*)(p3 + 8);
        uint4 g3 = *(const uint4*)(p3 + 12);
        {
            int ch = 8 + fch;
            float4 f0 = make_float4(__uint_as_float(pf0.x), __uint_as_float(pf0.y), __uint_as_float(pf0.z), __uint_as_float(pf0.w));
            float4 f1 = make_float4(__uint_as_float(pf1.x), __uint_as_float(pf1.y), __uint_as_float(pf1.z), __uint_as_float(pf1.w));
            float4 f2 = make_float4(__uint_as_float(pf2.x), __uint_as_float(pf2.y), __uint_as_float(pf2.z), __uint_as_float(pf2.w));
            float4 f3 = make_float4(__uint_as_float(pf3.x), __uint_as_float(pf3.y), __uint_as_float(pf3.z), __uint_as_float(pf3.w));
            unsigned off = (unsigned)fr * 256u + ((((unsigned)ch) ^ ((unsigned)fr & 7u)) << 4);
            *(uint4*)(Asm + off) = make_uint4(qpack4f(f0, scq, bi), qpack4f(f1, scq, bi),
                                              qpack4f(f2, scq, bi), qpack4f(f3, scq, bi));
        }
        {
            int ch = 12 + fch;
            float4 f0 = make_float4(__uint_as_float(g0.x), __uint_as_float(g0.y), __uint_as_float(g0.z), __uint_as_float(g0.w));
            float4 f1 = make_float4(__uint_as_float(g1.x), __uint_as_float(g1.y), __uint_as_float(g1.z), __uint_as_float(g1.w));
            float4 f2 = make_float4(__uint_as_float(g2.x), __uint_as_float(g2.y), __uint_as_float(g2.z), __uint_as_float(g2.w));
            float4 f3 = make_float4(__uint_as_float(g3.x), __uint_as_float(g3.y), __uint_as_float(g3.z), __uint_as_float(g3.w));
            unsigned off = (unsigned)fr * 256u + ((((unsigned)ch) ^ ((unsigned)fr & 7u)) << 4);
            *(uint4*)(Asm + off) = make_uint4(qpack4f(f0, scq, bi), qpack4f(f1, scq, bi),
                                              qpack4f(f2, scq, bi), qpack4f(f3, scq, bi));
        }
    } else {
        unsigned pk[4];
        qpack_s16(pf0, scq, bi, pk[0], pk[1]);
        qpack_s16(pf1, scq, bi, pk[2], pk[3]);
        unsigned off = (unsigned)fr * 256u + ((((unsigned)(8 + fch)) ^ ((unsigned)fr & 7u)) << 4);
        *(uint4*)(Asm + off) = make_uint4(pk[0], pk[1], pk[2], pk[3]);
        qpack_s16(pf2, scq, bi, pk[0], pk[1]);
        qpack_s16(pf3, scq, bi, pk[2], pk[3]);
        off = (unsigned)fr * 256u + ((((unsigned)(12 + fch)) ^ ((unsigned)fr & 7u)) << 4);
        *(uint4*)(Asm + off) = make_uint4(pk[0], pk[1], pk[2], pk[3]);
    }
    __syncthreads();        // A half1 visible

    // ---- MMA part 2: kk = 4..7 ----
#pragma unroll
    for (int kk = 4; kk < 8; ++kk) MMA_KSTEP(kk);
#undef MMA_KSTEP

    // ---- epilogue: relu+store int16, integer stats for next-layer LN ----
    const int qrow = lane >> 2, tig = lane & 3;

#pragma unroll
    for (int i = 0; i < 2; ++i) {
#pragma unroll
        for (int hi = 0; hi < 2; ++hi) {
            int lr = wm * 32 + i * 16 + hi * 8 + qrow;
            int grow = row0 + lr;
            if (!LAST) {
                int is1 = 0, imx = 0, imn = 0x7fffffff;
                float s2 = 0.f;
#pragma unroll
                for (int j = 0; j < 8; ++j) {
                    int q0 = max(acc[i][j][hi * 2], 0);       // exact int <= 32512
                    int q1 = max(acc[i][j][hi * 2 + 1], 0);
                    is1 += q0 + q1;
                    float f0 = (float)q0, f1 = (float)q1;
                    s2 = fmaf(f0, f0, s2);
                    s2 = fmaf(f1, f1, s2);
                    imx = max(imx, max(q0, q1));
                    imn = min(imn, min(q0, q1));
                    int col = wn * 64 + j * 8 + tig * 2;
                    *(unsigned*)(outs + (size_t)grow * DD + col) =
                        (unsigned)(q0 & 0xFFFF) | ((unsigned)q1 << 16);
                }
                is1 += __shfl_xor_sync(0xffffffffu, is1, 1);
                is1 += __shfl_xor_sync(0xffffffffu, is1, 2);
                s2  += __shfl_xor_sync(0xffffffffu, s2, 1);
                s2  += __shfl_xor_sync(0xffffffffu, s2, 2);
                imx  = max(imx, __shfl_xor_sync(0xffffffffu, imx, 1));
                imx  = max(imx, __shfl_xor_sync(0xffffffffu, imx, 2));
                imn  = min(imn, __shfl_xor_sync(0xffffffffu, imn, 1));
                imn  = min(imn, __shfl_xor_sync(0xffffffffu, imn, 2));
                if (tig == 0) {
                    risum[wn * 64 + lr] = is1;
                    rsq  [wn * 64 + lr] = s2;
                    rivx [wn * 64 + lr] = imx;
                    rivn [wn * 64 + lr] = imn;
                }
            } else {
#pragma unroll
                for (int j = 0; j < 8; ++j) {
                    float v0 = (float)acc[i][j][hi * 2]     * oscale;
                    float v1 = (float)acc[i][j][hi * 2 + 1] * oscale;
                    int col = wn * 64 + j * 8 + tig * 2;
                    *(float2*)(fout + (size_t)grow * DD + col) = make_float2(v0, v1);
                }
            }
        }
    }

    if constexpr (!LAST) {
        __syncthreads();
        if (tid < 64) {
            int a1i = (risum[tid] + risum[64 + tid]) + (risum[128 + tid] + risum[192 + tid]);
            float a2 = (rsq[tid] + rsq[64 + tid]) + (rsq[128 + tid] + rsq[192 + tid]);
            int mxi = max(max(rivx[tid], rivx[64 + tid]), max(rivx[128 + tid], rivx[192 + tid]));
            int mni = min(min(rivn[tid], rivn[64 + tid]), min(rivn[128 + tid], rivn[192 + tid]));
            float mu  = (float)a1i * oscale * (1.0f / 256.0f);
            float var = fmaxf(a2 * (oscale * oscale) * (1.0f / 256.0f) - mu * mu, 0.0f);
            float rsd = 1.0f / sqrtf(var + 1e-5f);
            g_mu[L + 1][row0 + tid]   = mu;
            g_rstd[L + 1][row0 + tid] = rsd;
            float mx = (float)mxi * oscale, mn = (float)mni * oscale;
            unsigned gu = __float_as_uint(fmaxf(mx - mu, mu - mn) * rsd);
#pragma unroll
            for (int o = 16; o; o >>= 1) gu = max(gu, __shfl_xor_sync(0xffffffffu, gu, o));
            if ((tid & 31) == 0) atomicMax(sgmax, gu);
        }
        __syncthreads();
        if (tid == 0) atomicMax(&g_gamma[L + 1], *sgmax);
    }
}

// ---------------- launch ----------------
extern "C" void kernel_launch(void* const* d_in, const int* in_sizes, int n_in,
                              void* d_out, int out_size) {
    const float* x  = (const float*)d_in[0];
    const float* W1 = (const float*)d_in[1];
    const float* W2 = (const float*)d_in[2];
    const float* W3 = (const float*)d_in[3];
    float* out = (float*)d_out;

    constexpr int SMEM = 20736 + 65536;  // 86272 B
    cudaFuncSetAttribute(layer_kernel<0>, cudaFuncAttributeMaxDynamicSharedMemorySize, SMEM);
    cudaFuncSetAttribute(layer_kernel<1>, cudaFuncAttributeMaxDynamicSharedMemorySize, SMEM);
    cudaFuncSetAttribute(layer_kernel<2>, cudaFuncAttributeMaxDynamicSharedMemorySize, SMEM);

    init_kernel<<<1, 32>>>();
    wprep_kernel<<<3, 1024>>>(W1, W2, W3);
    stats_kernel<<<BN / 16, 256>>>(x);
    layer_kernel<0><<<NBLK, 256, SMEM>>>(x, nullptr);
    layer_kernel<1><<<NBLK, 256, SMEM>>>(nullptr, nullptr);
    layer_kernel<2><<<NBLK, 256, SMEM>>>(nullptr, out);
}

// round 16
// speedup vs baseline: 1.0610x; 1.0610x over previous
#include <cuda_runtime.h>
#include <cuda_bf16.h>
#include <math.h>
#include <stdint.h>

#define BN 131072
#define DD 256
#define NBLK (BN / 64)

// ---------------- scratch (device globals: allocation-free) ----------------
__device__ __align__(16) short       g_hs1[(size_t)BN * DD];   // layer0 out (int16, exact)
__device__ __align__(16) short       g_hs2[(size_t)BN * DD];   // layer1 out
__device__ float                     g_mu[3][BN];
__device__ float                     g_rstd[3][BN];
__device__ unsigned                  g_gamma[3];
__device__ float                     g_beta[3];
__device__ __align__(16) signed char g_wb[3][DD * DD];         // +-1 int8, swizzled [n][k] layout

__device__ __forceinline__ uint32_t smem_u32(const void* p) {
    uint32_t a;
    asm("{ .reg .u64 t; cvta.to.shared.u64 t, %1; cvt.u32.u64 %0, t; }" : "=r"(a) : "l"(p));
    return a;
}

#define MBAR_INIT(mb, c) asm volatile("mbarrier.init.shared.b64 [%0], %1;" :: "r"(mb), "r"(c) : "memory")

#define MBAR_WAIT(mbar_smem_addr, phase_parity) do {                                         \
    uint32_t _mbar = (uint32_t)(mbar_smem_addr);                                             \
    uint32_t _parity = (uint32_t)(phase_parity);                                             \
    uint32_t _done;                                                                          \
    asm volatile(                                                                            \
        "{\n\t.reg .pred p;\n\t"                                                             \
        "mbarrier.try_wait.parity.shared.b64 p, [%1], %2;\n\t"                               \
        "selp.b32 %0, 1, 0, p;\n\t}"                                                         \
        : "=r"(_done) : "r"(_mbar), "r"(_parity) : "memory");                                \
    if (!_done) {                                                                            \
        asm volatile(                                                                        \
            "{\n\t.reg .pred P1;\n\t"                                                        \
            "WAIT_LOOP_%=:\n\t"                                                              \
            "mbarrier.try_wait.parity.shared.b64 P1, [%0], %1;\n\t"                          \
            "@P1 bra.uni WAIT_DONE_%=;\n\t"                                                  \
            "bra.uni WAIT_LOOP_%=;\n\t"                                                      \
            "WAIT_DONE_%=:\n\t}"                                                             \
            :: "r"(_mbar), "r"(_parity) : "memory");                                         \
    }                                                                                        \
} while (0)

// ---------------- weight prep: gamma init + alpha/beta + sign -> swizzled int8
// Layout: row n (256 B of k), chunk c (16B) stored at chunk (c ^ (n&7)).
__global__ void __launch_bounds__(1024) wprep_kernel(const float* __restrict__ W1,
                                                     const float* __restrict__ W2,
                                                     const float* __restrict__ W3) {
    const float* W = blockIdx.x == 0 ? W1 : (blockIdx.x == 1 ? W2 : W3);
    __shared__ float ps[32], pa[32];
    __shared__ float s_alpha;
    int tid = threadIdx.x;
    if (tid == 0) g_gamma[blockIdx.x] = 0u;   // fused init (ordered before stats/layers)
    float s = 0.f, sa = 0.f;
    for (int i = tid; i < DD * DD; i += 1024) {
        float w = W[i];
        s += w; sa += fabsf(w);
    }
#pragma unroll
    for (int o = 16; o; o >>= 1) {
        s  += __shfl_xor_sync(0xffffffffu, s,  o);
        sa += __shfl_xor_sync(0xffffffffu, sa, o);
    }
    if ((tid & 31) == 0) { ps[tid >> 5] = s; pa[tid >> 5] = sa; }
    __syncthreads();
    if (tid == 0) {
        float ts = 0.f, ta = 0.f;
        for (int i = 0; i < 32; i++) { ts += ps[i]; ta += pa[i]; }  // fixed order
        float alpha = ts / 65536.0f;
        g_beta[blockIdx.x] = fmaxf(ta / 65536.0f, 1e-8f);
        s_alpha = alpha;
    }
    __syncthreads();
    float alpha = s_alpha;
    signed char* wb = g_wb[blockIdx.x];
    for (int i = tid; i < DD * DD; i += 1024) {
        int n = i >> 8, k = i & 255;
        signed char v = ((W[i] - alpha) > 0.f) ? (signed char)1 : (signed char)-1;
        unsigned off = (unsigned)n * 256u + ((((unsigned)k >> 4) ^ ((unsigned)n & 7u)) << 4) + ((unsigned)k & 15u);
        wb[off] = v;
    }
}

// ---------------- stats for x: 2 rows/warp (MLP=4) ------------------------
__global__ void __launch_bounds__(256) stats_kernel(const float* __restrict__ x) {
    __shared__ unsigned sg;
    int tid = threadIdx.x;
    if (tid == 0) sg = 0u;
    __syncthreads();
    int warp = tid >> 5, lane = tid & 31;
    size_t row = (size_t)blockIdx.x * 16 + warp * 2;
    const float* xr0 = x + row * DD;
    const float* xr1 = xr0 + DD;
    float4 a0 = *(const float4*)(xr0 + lane * 4);
    float4 a1 = *(const float4*)(xr1 + lane * 4);
    float4 b0 = *(const float4*)(xr0 + 128 + lane * 4);
    float4 b1 = *(const float4*)(xr1 + 128 + lane * 4);
    float s0 = ((a0.x + a0.y) + (a0.z + a0.w)) + ((b0.x + b0.y) + (b0.z + b0.w));
    float s1 = ((a1.x + a1.y) + (a1.z + a1.w)) + ((b1.x + b1.y) + (b1.z + b1.w));
#pragma unroll
    for (int o = 16; o; o >>= 1) {
        s0 += __shfl_xor_sync(0xffffffffu, s0, o);
        s1 += __shfl_xor_sync(0xffffffffu, s1, o);
    }
    float mu0 = s0 * (1.0f / 256.0f);
    float mu1 = s1 * (1.0f / 256.0f);
    float ss0 = 0.f, mx0 = 0.f, ss1 = 0.f, mx1 = 0.f, d;
    d = a0.x - mu0; ss0 += d * d; mx0 = fmaxf(mx0, fabsf(d));
    d = a0.y - mu0; ss0 += d * d; mx0 = fmaxf(mx0, fabsf(d));
    d = a0.z - mu0; ss0 += d * d; mx0 = fmaxf(mx0, fabsf(d));
    d = a0.w - mu0; ss0 += d * d; mx0 = fmaxf(mx0, fabsf(d));
    d = b0.x - mu0; ss0 += d * d; mx0 = fmaxf(mx0, fabsf(d));
    d = b0.y - mu0; ss0 += d * d; mx0 = fmaxf(mx0, fabsf(d));
    d = b0.z - mu0; ss0 += d * d; mx0 = fmaxf(mx0, fabsf(d));
    d = b0.w - mu0; ss0 += d * d; mx0 = fmaxf(mx0, fabsf(d));
    d = a1.x - mu1; ss1 += d * d; mx1 = fmaxf(mx1, fabsf(d));
    d = a1.y - mu1; ss1 += d * d; mx1 = fmaxf(mx1, fabsf(d));
    d = a1.z - mu1; ss1 += d * d; mx1 = fmaxf(mx1, fabsf(d));
    d = a1.w - mu1; ss1 += d * d; mx1 = fmaxf(mx1, fabsf(d));
    d = b1.x - mu1; ss1 += d * d; mx1 = fmaxf(mx1, fabsf(d));
    d = b1.y - mu1; ss1 += d * d; mx1 = fmaxf(mx1, fabsf(d));
    d = b1.z - mu1; ss1 += d * d; mx1 = fmaxf(mx1, fabsf(d));
    d = b1.w - mu1; ss1 += d * d; mx1 = fmaxf(mx1, fabsf(d));
#pragma unroll
    for (int o = 16; o; o >>= 1) {
        ss0 += __shfl_xor_sync(0xffffffffu, ss0, o);
        ss1 += __shfl_xor_sync(0xffffffffu, ss1, o);
        mx0  = fmaxf(mx0, __shfl_xor_sync(0xffffffffu, mx0, o));
        mx1  = fmaxf(mx1, __shfl_xor_sync(0xffffffffu, mx1, o));
    }
    float rsd0 = 1.0f / sqrtf(ss0 * (1.0f / 256.0f) + 1e-5f);
    float rsd1 = 1.0f / sqrtf(ss1 * (1.0f / 256.0f) + 1e-5f);
    if (lane == 0) {
        g_mu[0][row]       = mu0;
        g_mu[0][row + 1]   = mu1;
        g_rstd[0][row]     = rsd0;
        g_rstd[0][row + 1] = rsd1;
        atomicMax(&sg, __float_as_uint(fmaxf(mx0 * rsd0, mx1 * rsd1)));
    }
    __syncthreads();
    if (tid == 0) atomicMax(&g_gamma[0], sg);
}

// ---------------- fused layer: LN+quant -> IMMA (ldmatrix) -> epilogue ----
// CTA: 64 rows x 256 cols, K=256. 256 threads = 8 warps (2M x 4N), warp 32x64.
// B arrives via cp.async.bulk (overlaps A-fill). 2 CTAs / SM.
// smem: stats 4KB | sgmax | mbar | A int8 16KB @4352 | B int8 64KB @20736. 86272 B.
template <int L>
__global__ void __launch_bounds__(256, 2) layer_kernel(const float* __restrict__ xin,
                                                       float* __restrict__ fout) {
    constexpr bool LAST = (L == 2);
    extern __shared__ char smem[];
    int*      risum = (int*)smem;                   // [4][64]
    float*    rsq   = (float*)(smem + 1024);        // [4][64]
    int*      rivx  = (int*)(smem + 2048);          // [4][64]
    int*      rivn  = (int*)(smem + 3072);          // [4][64]
    unsigned* sgmax = (unsigned*)(smem + 4096);
    char*     Asm   = smem + 4352;
    char*     Bsm   = smem + 20736;
    const uint32_t A_u  = smem_u32(Asm);
    const uint32_t B_u  = smem_u32(Bsm);
    const uint32_t MBAR = smem_u32(smem + 4104);

    const int tid = threadIdx.x;
    const int warp = tid >> 5, lane = tid & 31;
    const int row0 = blockIdx.x * 64;

    // ---- B: single-thread async bulk copy (overlaps the A-fill below) ----
    if (tid == 0) {
        *sgmax = 0u;
        MBAR_INIT(MBAR, 1);
        asm volatile("mbarrier.arrive.expect_tx.shared.b64 _, [%0], %1;"
                     :: "r"(MBAR), "r"(65536u) : "memory");
        asm volatile("cp.async.bulk.shared::cta.global.mbarrier::complete_tx::bytes "
                     "[%0], [%1], %2, [%3];"
                     :: "r"(B_u), "l"((const void*)g_wb[L]), "r"(65536u), "r"(MBAR)
                     : "memory");
    }

    const float gamma  = fmaxf(__uint_as_float(g_gamma[L]), 1e-8f);
    const float qs     = 127.0f / gamma;
    const float oscale = g_beta[L] * gamma / 127.0f;
    float poscale = 0.f;
    if (L > 0) poscale = g_beta[L - 1] * fmaxf(__uint_as_float(g_gamma[L - 1]), 1e-8f) / 127.0f;

    const short* sprev = (L == 1) ? g_hs1 : g_hs2;
    const float* muL = g_mu[L];
    const float* rsL = g_rstd[L];
    short* outs = (L == 0) ? g_hs1 : g_hs2;

    // ---- A: load -> fused LN+quant -> swizzled smem (16B chunks) ----
#pragma unroll
    for (int it = 0; it < 4; ++it) {
        int c = tid + it * 256;           // 1024 chunks (64 rows x 16)
        int r = c >> 4, ch = c & 15;
        int grow = row0 + r;
        float sc = rsL[grow] * qs;
        float bi = -muL[grow] * sc;
        unsigned pk[4];
        if (L == 0) {
            const float* p = xin + (size_t)grow * DD + ch * 16;
#pragma unroll
            for (int q = 0; q < 4; ++q) {
                float4 f = *(const float4*)(p + q * 4);
                unsigned w = 0;
                float t;
                t = fminf(fmaxf(fmaf(f.x, sc, bi), -127.f), 127.f);
                w |= ((unsigned)__float2int_rn(t) & 0xFFu);
                t = fminf(fmaxf(fmaf(f.y, sc, bi), -127.f), 127.f);
                w |= ((unsigned)__float2int_rn(t) & 0xFFu) << 8;
                t = fminf(fmaxf(fmaf(f.z, sc, bi), -127.f), 127.f);
                w |= ((unsigned)__float2int_rn(t) & 0xFFu) << 16;
                t = fminf(fmaxf(fmaf(f.w, sc, bi), -127.f), 127.f);
                w |= ((unsigned)__float2int_rn(t) & 0xFFu) << 24;
                pk[q] = w;
            }
        } else {
            float sc2 = poscale * sc;
            const short* p = sprev + (size_t)grow * DD + ch * 16;
#pragma unroll
            for (int q = 0; q < 2; ++q) {
                uint4 u = *(const uint4*)(p + q * 8);
                unsigned uu[4] = {u.x, u.y, u.z, u.w};
#pragma unroll
                for (int h = 0; h < 2; ++h) {
                    unsigned w = 0;
#pragma unroll
                    for (int b = 0; b < 2; ++b) {
                        unsigned raw = uu[h * 2 + b];
                        float t0 = fminf(fmaxf(fmaf((float)(short)(raw & 0xFFFF), sc2, bi), -127.f), 127.f);
                        float t1 = fminf(fmaxf(fmaf((float)(short)(raw >> 16),    sc2, bi), -127.f), 127.f);
                        w |= ((unsigned)__float2int_rn(t0) & 0xFFu) << (16 * b);
                        w |= ((unsigned)__float2int_rn(t1) & 0xFFu) << (16 * b + 8);
                    }
                    pk[q * 2 + h] = w;
                }
            }
        }
        unsigned off = (unsigned)r * 256u + ((((unsigned)ch) ^ ((unsigned)r & 7u)) << 4);
        *(uint4*)(Asm + off) = make_uint4(pk[0], pk[1], pk[2], pk[3]);
    }
    __syncthreads();        // A visible to all warps (and MBAR init to all threads)
    MBAR_WAIT(MBAR, 0);     // B bulk copy complete

    // ---- MMA mainloop: warp tile 32(M) x 64(N), K=256 in 8 k32 steps ----
    const int wm = warp & 1;        // 2 M-groups of 32 rows
    const int wn = warp >> 1;       // 4 N-groups of 64 cols

    uint32_t a_base[2]; unsigned a_x7[2];
#pragma unroll
    for (int i = 0; i < 2; ++i) {
        int r = wm * 32 + i * 16 + (lane & 15);
        a_base[i] = A_u + (unsigned)r * 256u;
        a_x7[i] = (unsigned)r & 7u;
    }
    uint32_t b_base[4]; unsigned b_x7[4];
#pragma unroll
    for (int jp = 0; jp < 4; ++jp) {
        int n = wn * 64 + jp * 16 + ((lane >> 4) << 3) + (lane & 7);
        b_base[jp] = B_u + (unsigned)n * 256u;
        b_x7[jp] = (unsigned)n & 7u;
    }
    const unsigned a_ck = (unsigned)(lane >> 4);        // 0/1: k16-half
    const unsigned b_ck = (unsigned)((lane >> 3) & 1);  // 0/1

    int acc[2][8][4];
#pragma unroll
    for (int i = 0; i < 2; i++)
#pragma unroll
        for (int j = 0; j < 8; j++)
#pragma unroll
            for (int r = 0; r < 4; r++) acc[i][j][r] = 0;

#pragma unroll
    for (int kk = 0; kk < 8; ++kk) {
        unsigned a[2][4];
#pragma unroll
        for (int i = 0; i < 2; ++i) {
            uint32_t ad = a_base[i] + ((((unsigned)(kk * 2) + a_ck) ^ a_x7[i]) << 4);
            asm volatile("ldmatrix.sync.aligned.m8n8.x4.shared.b16 {%0,%1,%2,%3}, [%4];"
                         : "=r"(a[i][0]), "=r"(a[i][1]), "=r"(a[i][2]), "=r"(a[i][3])
                         : "r"(ad));
        }
#pragma unroll
        for (int jp = 0; jp < 4; ++jp) {
            uint32_t bd = b_base[jp] + ((((unsigned)(kk * 2) + b_ck) ^ b_x7[jp]) << 4);
            unsigned rb[4];
            asm volatile("ldmatrix.sync.aligned.m8n8.x4.shared.b16 {%0,%1,%2,%3}, [%4];"
                         : "=r"(rb[0]), "=r"(rb[1]), "=r"(rb[2]), "=r"(rb[3])
                         : "r"(bd));
#pragma unroll
            for (int i = 0; i < 2; ++i) {
                asm volatile(
                    "mma.sync.aligned.m16n8k32.row.col.s32.s8.s8.s32 "
                    "{%0,%1,%2,%3}, {%4,%5,%6,%7}, {%8,%9}, {%0,%1,%2,%3};\n"
                    : "+r"(acc[i][2 * jp][0]), "+r"(acc[i][2 * jp][1]),
                      "+r"(acc[i][2 * jp][2]), "+r"(acc[i][2 * jp][3])
                    : "r"(a[i][0]), "r"(a[i][1]), "r"(a[i][2]), "r"(a[i][3]),
                      "r"(rb[0]), "r"(rb[1]));
                asm volatile(
                    "mma.sync.aligned.m16n8k32.row.col.s32.s8.s8.s32 "
                    "{%0,%1,%2,%3}, {%4,%5,%6,%7}, {%8,%9}, {%0,%1,%2,%3};\n"
                    : "+r"(acc[i][2 * jp + 1][0]), "+r"(acc[i][2 * jp + 1][1]),
                      "+r"(acc[i][2 * jp + 1][2]), "+r"(acc[i][2 * jp + 1][3])
                    : "r"(a[i][0]), "r"(a[i][1]), "r"(a[i][2]), "r"(a[i][3]),
                      "r"(rb[2]), "r"(rb[3]));
            }
        }
    }

    // ---- epilogue: relu+store int16, integer stats for next-layer LN ----
    const int qrow = lane >> 2, tig = lane & 3;

#pragma unroll
    for (int i = 0; i < 2; ++i) {
#pragma unroll
        for (int hi = 0; hi < 2; ++hi) {
            int lr = wm * 32 + i * 16 + hi * 8 + qrow;
            int grow = row0 + lr;
            if (!LAST) {
                int is1 = 0, imx = 0, imn = 0x7fffffff;
                float s2 = 0.f;
#pragma unroll
                for (int j = 0; j < 8; ++j) {
                    int q0 = max(acc[i][j][hi * 2], 0);       // exact int <= 32512
                    int q1 = max(acc[i][j][hi * 2 + 1], 0);
                    is1 += q0 + q1;
                    float f0 = (float)q0, f1 = (float)q1;
                    s2 = fmaf(f0, f0, s2);
                    s2 = fmaf(f1, f1, s2);
                    imx = max(imx, max(q0, q1));
                    imn = min(imn, min(q0, q1));
                    int col = wn * 64 + j * 8 + tig * 2;
                    *(unsigned*)(outs + (size_t)grow * DD + col) =
                        (unsigned)(q0 & 0xFFFF) | ((unsigned)q1 << 16);
                }
                is1 += __shfl_xor_sync(0xffffffffu, is1, 1);
                is1 += __shfl_xor_sync(0xffffffffu, is1, 2);
                s2  += __shfl_xor_sync(0xffffffffu, s2, 1);
                s2  += __shfl_xor_sync(0xffffffffu, s2, 2);
                imx  = max(imx, __shfl_xor_sync(0xffffffffu, imx, 1));
                imx  = max(imx, __shfl_xor_sync(0xffffffffu, imx, 2));
                imn  = min(imn, __shfl_xor_sync(0xffffffffu, imn, 1));
                imn  = min(imn, __shfl_xor_sync(0xffffffffu, imn, 2));
                if (tig == 0) {
                    risum[wn * 64 + lr] = is1;
                    rsq  [wn * 64 + lr] = s2;
                    rivx [wn * 64 + lr] = imx;
                    rivn [wn * 64 + lr] = imn;
                }
            } else {
#pragma unroll
                for (int j = 0; j < 8; ++j) {
                    float v0 = (float)acc[i][j][hi * 2]     * oscale;
                    float v1 = (float)acc[i][j][hi * 2 + 1] * oscale;
                    int col = wn * 64 + j * 8 + tig * 2;
                    *(float2*)(fout + (size_t)grow * DD + col) = make_float2(v0, v1);
                }
            }
        }
    }

    if constexpr (!LAST) {
        __syncthreads();
        if (tid < 64) {
            int a1i = (risum[tid] + risum[64 + tid]) + (risum[128 + tid] + risum[192 + tid]);
            float a2 = (rsq[tid] + rsq[64 + tid]) + (rsq[128 + tid] + rsq[192 + tid]);
            int mxi = max(max(rivx[tid], rivx[64 + tid]), max(rivx[128 + tid], rivx[192 + tid]));
            int mni = min(min(rivn[tid], rivn[64 + tid]), min(rivn[128 + tid], rivn[192 + tid]));
            float mu  = (float)a1i * oscale * (1.0f / 256.0f);
            float var = fmaxf(a2 * (oscale * oscale) * (1.0f / 256.0f) - mu * mu, 0.0f);
            float rsd = 1.0f / sqrtf(var + 1e-5f);
            g_mu[L + 1][row0 + tid]   = mu;
            g_rstd[L + 1][row0 + tid] = rsd;
            float mx = (float)mxi * oscale, mn = (float)mni * oscale;
            unsigned gu = __float_as_uint(fmaxf(mx - mu, mu - mn) * rsd);
#pragma unroll
            for (int o = 16; o; o >>= 1) gu = max(gu, __shfl_xor_sync(0xffffffffu, gu, o));
            if ((tid & 31) == 0) atomicMax(sgmax, gu);
        }
        __syncthreads();
        if (tid == 0) atomicMax(&g_gamma[L + 1], *sgmax);
    }
}

// ---------------- launch ----------------
extern "C" void kernel_launch(void* const* d_in, const int* in_sizes, int n_in,
                              void* d_out, int out_size) {
    const float* x  = (const float*)d_in[0];
    const float* W1 = (const float*)d_in[1];
    const float* W2 = (const float*)d_in[2];
    const float* W3 = (const float*)d_in[3];
    float* out = (float*)d_out;

    constexpr int SMEM = 20736 + 65536;  // 86272 B
    cudaFuncSetAttribute(layer_kernel<0>, cudaFuncAttributeMaxDynamicSharedMemorySize, SMEM);
    cudaFuncSetAttribute(layer_kernel<1>, cudaFuncAttributeMaxDynamicSharedMemorySize, SMEM);
    cudaFuncSetAttribute(layer_kernel<2>, cudaFuncAttributeMaxDynamicSharedMemorySize, SMEM);

    wprep_kernel<<<3, 1024>>>(W1, W2, W3);
    stats_kernel<<<BN / 16, 256>>>(x);
    layer_kernel<0><<<NBLK, 256, SMEM>>>(x, nullptr);
    layer_kernel<1><<<NBLK, 256, SMEM>>>(nullptr, nullptr);
    layer_kernel<2><<<NBLK, 256, SMEM>>>(nullptr, out);
}

// round 17
// speedup vs baseline: 1.0625x; 1.0014x over previous
#include <cuda_runtime.h>
#include <cuda_bf16.h>
#include <math.h>
#include <stdint.h>

#define BN 131072
#define DD 256
#define NBLK (BN / 64)

// ---------------- scratch (device globals: allocation-free) ----------------
__device__ __align__(16) short       g_hs1[(size_t)BN * DD];   // layer0 out (int16, exact)
__device__ __align__(16) short       g_hs2[(size_t)BN * DD];   // layer1 out
__device__ float                     g_mu[3][BN];
__device__ float                     g_rstd[3][BN];
__device__ unsigned                  g_gamma[3];
__device__ float                     g_beta[3];
__device__ __align__(16) signed char g_wb[3][DD * DD];         // +-1 int8, swizzled [n][k] layout

__device__ __forceinline__ uint32_t smem_u32(const void* p) {
    uint32_t a;
    asm("{ .reg .u64 t; cvta.to.shared.u64 t, %1; cvt.u32.u64 %0, t; }" : "=r"(a) : "l"(p));
    return a;
}

#define MBAR_INIT(mb, c) asm volatile("mbarrier.init.shared.b64 [%0], %1;" :: "r"(mb), "r"(c) : "memory")

#define MBAR_WAIT(mbar_smem_addr, phase_parity) do {                                         \
    uint32_t _mbar = (uint32_t)(mbar_smem_addr);                                             \
    uint32_t _parity = (uint32_t)(phase_parity);                                             \
    uint32_t _done;                                                                          \
    asm volatile(                                                                            \
        "{\n\t.reg .pred p;\n\t"                                                             \
        "mbarrier.try_wait.parity.shared.b64 p, [%1], %2;\n\t"                               \
        "selp.b32 %0, 1, 0, p;\n\t}"                                                         \
        : "=r"(_done) : "r"(_mbar), "r"(_parity) : "memory");                                \
    if (!_done) {                                                                            \
        asm volatile(                                                                        \
            "{\n\t.reg .pred P1;\n\t"                                                        \
            "WAIT_LOOP_%=:\n\t"                                                              \
            "mbarrier.try_wait.parity.shared.b64 P1, [%0], %1;\n\t"                          \
            "@P1 bra.uni WAIT_DONE_%=;\n\t"                                                  \
            "bra.uni WAIT_LOOP_%=;\n\t"                                                      \
            "WAIT_DONE_%=:\n\t}"                                                             \
            :: "r"(_mbar), "r"(_parity) : "memory");                                         \
    }                                                                                        \
} while (0)

// quantize 4 floats -> packed s8x4 (bytes LSB..MSB = q0..q3).
// No explicit clamp needed: gamma is the GLOBAL absmax, so |x*sc+bi| <= 127(1+eps);
// cvt.rni + s8 saturate is bit-identical to the reference clip->round (-128 unreachable).
__device__ __forceinline__ unsigned qpack4(float a, float b, float c, float d,
                                           float sc, float bi) {
    int q0 = __float2int_rn(fmaf(a, sc, bi));
    int q1 = __float2int_rn(fmaf(b, sc, bi));
    int q2 = __float2int_rn(fmaf(c, sc, bi));
    int q3 = __float2int_rn(fmaf(d, sc, bi));
    unsigned t, r;
    asm("cvt.pack.sat.s8.s32.b32 %0, %1, %2, %3;" : "=r"(t) : "r"(q3), "r"(q2), "r"(0));
    asm("cvt.pack.sat.s8.s32.b32 %0, %1, %2, %3;" : "=r"(r) : "r"(q1), "r"(q0), "r"(t));
    return r;
}

__device__ __forceinline__ unsigned qpack4f(float4 f, float sc, float bi) {
    return qpack4(f.x, f.y, f.z, f.w, sc, bi);
}

// quantize 8 int16 (one uint4) -> 2 packed s8x4 words
__device__ __forceinline__ void qpack_s16(uint4 u, float sc, float bi,
                                          unsigned& w0, unsigned& w1) {
    w0 = qpack4((float)(short)(u.x & 0xFFFF), (float)(short)(u.x >> 16),
                (float)(short)(u.y & 0xFFFF), (float)(short)(u.y >> 16), sc, bi);
    w1 = qpack4((float)(short)(u.z & 0xFFFF), (float)(short)(u.z >> 16),
                (float)(short)(u.w & 0xFFFF), (float)(short)(u.w >> 16), sc, bi);
}

// ---------------- weight prep: gamma init + alpha/beta + sign -> swizzled int8
// Layout: row n (256 B of k), chunk c (16B) stored at chunk (c ^ (n&7)).
__global__ void __launch_bounds__(1024) wprep_kernel(const float* __restrict__ W1,
                                                     const float* __restrict__ W2,
                                                     const float* __restrict__ W3) {
    const float* W = blockIdx.x == 0 ? W1 : (blockIdx.x == 1 ? W2 : W3);
    __shared__ float ps[32], pa[32];
    __shared__ float s_alpha;
    int tid = threadIdx.x;
    if (tid == 0) g_gamma[blockIdx.x] = 0u;   // fused init (ordered before stats/layers)
    float s = 0.f, sa = 0.f;
    for (int i = tid; i < DD * DD; i += 1024) {
        float w = W[i];
        s += w; sa += fabsf(w);
    }
#pragma unroll
    for (int o = 16; o; o >>= 1) {
        s  += __shfl_xor_sync(0xffffffffu, s,  o);
        sa += __shfl_xor_sync(0xffffffffu, sa, o);
    }
    if ((tid & 31) == 0) { ps[tid >> 5] = s; pa[tid >> 5] = sa; }
    __syncthreads();
    if (tid == 0) {
        float ts = 0.f, ta = 0.f;
        for (int i = 0; i < 32; i++) { ts += ps[i]; ta += pa[i]; }  // fixed order
        float alpha = ts / 65536.0f;
        g_beta[blockIdx.x] = fmaxf(ta / 65536.0f, 1e-8f);
        s_alpha = alpha;
    }
    __syncthreads();
    float alpha = s_alpha;
    signed char* wb = g_wb[blockIdx.x];
    for (int i = tid; i < DD * DD; i += 1024) {
        int n = i >> 8, k = i & 255;
        signed char v = ((W[i] - alpha) > 0.f) ? (signed char)1 : (signed char)-1;
        unsigned off = (unsigned)n * 256u + ((((unsigned)k >> 4) ^ ((unsigned)n & 7u)) << 4) + ((unsigned)k & 15u);
        wb[off] = v;
    }
}

// ---------------- stats for x: 2 rows/warp (MLP=4) ------------------------
__global__ void __launch_bounds__(256) stats_kernel(const float* __restrict__ x) {
    __shared__ unsigned sg;
    int tid = threadIdx.x;
    if (tid == 0) sg = 0u;
    __syncthreads();
    int warp = tid >> 5, lane = tid & 31;
    size_t row = (size_t)blockIdx.x * 16 + warp * 2;
    const float* xr0 = x + row * DD;
    const float* xr1 = xr0 + DD;
    float4 a0 = *(const float4*)(xr0 + lane * 4);
    float4 a1 = *(const float4*)(xr1 + lane * 4);
    float4 b0 = *(const float4*)(xr0 + 128 + lane * 4);
    float4 b1 = *(const float4*)(xr1 + 128 + lane * 4);
    float s0 = ((a0.x + a0.y) + (a0.z + a0.w)) + ((b0.x + b0.y) + (b0.z + b0.w));
    float s1 = ((a1.x + a1.y) + (a1.z + a1.w)) + ((b1.x + b1.y) + (b1.z + b1.w));
#pragma unroll
    for (int o = 16; o; o >>= 1) {
        s0 += __shfl_xor_sync(0xffffffffu, s0, o);
        s1 += __shfl_xor_sync(0xffffffffu, s1, o);
    }
    float mu0 = s0 * (1.0f / 256.0f);
    float mu1 = s1 * (1.0f / 256.0f);
    float ss0 = 0.f, mx0 = 0.f, ss1 = 0.f, mx1 = 0.f, d;
    d = a0.x - mu0; ss0 += d * d; mx0 = fmaxf(mx0, fabsf(d));
    d = a0.y - mu0; ss0 += d * d; mx0 = fmaxf(mx0, fabsf(d));
    d = a0.z - mu0; ss0 += d * d; mx0 = fmaxf(mx0, fabsf(d));
    d = a0.w - mu0; ss0 += d * d; mx0 = fmaxf(mx0, fabsf(d));
    d = b0.x - mu0; ss0 += d * d; mx0 = fmaxf(mx0, fabsf(d));
    d = b0.y - mu0; ss0 += d * d; mx0 = fmaxf(mx0, fabsf(d));
    d = b0.z - mu0; ss0 += d * d; mx0 = fmaxf(mx0, fabsf(d));
    d = b0.w - mu0; ss0 += d * d; mx0 = fmaxf(mx0, fabsf(d));
    d = a1.x - mu1; ss1 += d * d; mx1 = fmaxf(mx1, fabsf(d));
    d = a1.y - mu1; ss1 += d * d; mx1 = fmaxf(mx1, fabsf(d));
    d = a1.z - mu1; ss1 += d * d; mx1 = fmaxf(mx1, fabsf(d));
    d = a1.w - mu1; ss1 += d * d; mx1 = fmaxf(mx1, fabsf(d));
    d = b1.x - mu1; ss1 += d * d; mx1 = fmaxf(mx1, fabsf(d));
    d = b1.y - mu1; ss1 += d * d; mx1 = fmaxf(mx1, fabsf(d));
    d = b1.z - mu1; ss1 += d * d; mx1 = fmaxf(mx1, fabsf(d));
    d = b1.w - mu1; ss1 += d * d; mx1 = fmaxf(mx1, fabsf(d));
#pragma unroll
    for (int o = 16; o; o >>= 1) {
        ss0 += __shfl_xor_sync(0xffffffffu, ss0, o);
        ss1 += __shfl_xor_sync(0xffffffffu, ss1, o);
        mx0  = fmaxf(mx0, __shfl_xor_sync(0xffffffffu, mx0, o));
        mx1  = fmaxf(mx1, __shfl_xor_sync(0xffffffffu, mx1, o));
    }
    float rsd0 = 1.0f / sqrtf(ss0 * (1.0f / 256.0f) + 1e-5f);
    float rsd1 = 1.0f / sqrtf(ss1 * (1.0f / 256.0f) + 1e-5f);
    if (lane == 0) {
        g_mu[0][row]       = mu0;
        g_mu[0][row + 1]   = mu1;
        g_rstd[0][row]     = rsd0;
        g_rstd[0][row + 1] = rsd1;
        atomicMax(&sg, __float_as_uint(fmaxf(mx0 * rsd0, mx1 * rsd1)));
    }
    __syncthreads();
    if (tid == 0) atomicMax(&g_gamma[0], sg);
}

// ---------------- fused layer: LN+quant -> IMMA (ldmatrix) -> epilogue ----
// CTA: 64 rows x 256 cols, K=256. 256 threads = 8 warps (2M x 4N), warp 32x64.
// B arrives via cp.async.bulk (overlaps A-fill). 2 CTAs / SM.
// smem: stats 4KB | mbar | A int8 16KB @4352 | B int8 64KB @20736. 86272 B.
template <int L>
__global__ void __launch_bounds__(256, 2) layer_kernel(const float* __restrict__ xin,
                                                       float* __restrict__ fout) {
    constexpr bool LAST = (L == 2);
    extern __shared__ char smem[];
    int*      risum = (int*)smem;                   // [4][64]
    float*    rsq   = (float*)(smem + 1024);        // [4][64]
    int*      rivx  = (int*)(smem + 2048);          // [4][64]
    int*      rivn  = (int*)(smem + 3072);          // [4][64]
    char*     Asm   = smem + 4352;
    char*     Bsm   = smem + 20736;
    const uint32_t A_u  = smem_u32(Asm);
    const uint32_t B_u  = smem_u32(Bsm);
    const uint32_t MBAR = smem_u32(smem + 4104);

    const int tid = threadIdx.x;
    const int warp = tid >> 5, lane = tid & 31;
    const int row0 = blockIdx.x * 64;

    // ---- B: single-thread async bulk copy (overlaps the A-fill below) ----
    if (tid == 0) {
        MBAR_INIT(MBAR, 1);
        asm volatile("mbarrier.arrive.expect_tx.shared.b64 _, [%0], %1;"
                     :: "r"(MBAR), "r"(65536u) : "memory");
        asm volatile("cp.async.bulk.shared::cta.global.mbarrier::complete_tx::bytes "
                     "[%0], [%1], %2, [%3];"
                     :: "r"(B_u), "l"((const void*)g_wb[L]), "r"(65536u), "r"(MBAR)
                     : "memory");
    }

    const float gamma  = fmaxf(__uint_as_float(g_gamma[L]), 1e-8f);
    const float qs     = 127.0f / gamma;
    const float oscale = g_beta[L] * gamma / 127.0f;
    float poscale = 0.f;
    if (L > 0) poscale = g_beta[L - 1] * fmaxf(__uint_as_float(g_gamma[L - 1]), 1e-8f) / 127.0f;

    const short* sprev = (L == 1) ? g_hs1 : g_hs2;
    const float* muL = g_mu[L];
    const float* rsL = g_rstd[L];
    short* outs = (L == 0) ? g_hs1 : g_hs2;

    // ---- A: load -> fused LN+quant -> swizzled smem (16B chunks) ----
#pragma unroll
    for (int it = 0; it < 4; ++it) {
        int c = tid + it * 256;           // 1024 chunks (64 rows x 16)
        int r = c >> 4, ch = c & 15;
        int grow = row0 + r;
        float sc = rsL[grow] * qs;
        float bi = -muL[grow] * sc;
        unsigned pk[4];
        if (L == 0) {
            const float* p = xin + (size_t)grow * DD + ch * 16;
            pk[0] = qpack4f(*(const float4*)(p),      sc, bi);
            pk[1] = qpack4f(*(const float4*)(p + 4),  sc, bi);
            pk[2] = qpack4f(*(const float4*)(p + 8),  sc, bi);
            pk[3] = qpack4f(*(const float4*)(p + 12), sc, bi);
        } else {
            float sc2 = poscale * sc;
            const short* p = sprev + (size_t)grow * DD + ch * 16;
            qpack_s16(*(const uint4*)(p),     sc2, bi, pk[0], pk[1]);
            qpack_s16(*(const uint4*)(p + 8), sc2, bi, pk[2], pk[3]);
        }
        unsigned off = (unsigned)r * 256u + ((((unsigned)ch) ^ ((unsigned)r & 7u)) << 4);
        *(uint4*)(Asm + off) = make_uint4(pk[0], pk[1], pk[2], pk[3]);
    }
    __syncthreads();        // A visible to all warps (and MBAR init to all threads)
    MBAR_WAIT(MBAR, 0);     // B bulk copy complete

    // ---- MMA mainloop: warp tile 32(M) x 64(N), K=256 in 8 k32 steps ----
    const int wm = warp & 1;        // 2 M-groups of 32 rows
    const int wn = warp >> 1;       // 4 N-groups of 64 cols

    uint32_t a_base[2]; unsigned a_x7[2];
#pragma unroll
    for (int i = 0; i < 2; ++i) {
        int r = wm * 32 + i * 16 + (lane & 15);
        a_base[i] = A_u + (unsigned)r * 256u;
        a_x7[i] = (unsigned)r & 7u;
    }
    uint32_t b_base[4]; unsigned b_x7[4];
#pragma unroll
    for (int jp = 0; jp < 4; ++jp) {
        int n = wn * 64 + jp * 16 + ((lane >> 4) << 3) + (lane & 7);
        b_base[jp] = B_u + (unsigned)n * 256u;
        b_x7[jp] = (unsigned)n & 7u;
    }
    const unsigned a_ck = (unsigned)(lane >> 4);        // 0/1: k16-half
    const unsigned b_ck = (unsigned)((lane >> 3) & 1);  // 0/1

    int acc[2][8][4];
#pragma unroll
    for (int i = 0; i < 2; i++)
#pragma unroll
        for (int j = 0; j < 8; j++)
#pragma unroll
            for (int r = 0; r < 4; r++) acc[i][j][r] = 0;

#pragma unroll
    for (int kk = 0; kk < 8; ++kk) {
        unsigned a[2][4];
#pragma unroll
        for (int i = 0; i < 2; ++i) {
            uint32_t ad = a_base[i] + ((((unsigned)(kk * 2) + a_ck) ^ a_x7[i]) << 4);
            asm volatile("ldmatrix.sync.aligned.m8n8.x4.shared.b16 {%0,%1,%2,%3}, [%4];"
                         : "=r"(a[i][0]), "=r"(a[i][1]), "=r"(a[i][2]), "=r"(a[i][3])
                         : "r"(ad));
        }
#pragma unroll
        for (int jp = 0; jp < 4; ++jp) {
            uint32_t bd = b_base[jp] + ((((unsigned)(kk * 2) + b_ck) ^ b_x7[jp]) << 4);
            unsigned rb[4];
            asm volatile("ldmatrix.sync.aligned.m8n8.x4.shared.b16 {%0,%1,%2,%3}, [%4];"
                         : "=r"(rb[0]), "=r"(rb[1]), "=r"(rb[2]), "=r"(rb[3])
                         : "r"(bd));
#pragma unroll
            for (int i = 0; i < 2; ++i) {
                asm volatile(
                    "mma.sync.aligned.m16n8k32.row.col.s32.s8.s8.s32 "
                    "{%0,%1,%2,%3}, {%4,%5,%6,%7}, {%8,%9}, {%0,%1,%2,%3};\n"
                    : "+r"(acc[i][2 * jp][0]), "+r"(acc[i][2 * jp][1]),
                      "+r"(acc[i][2 * jp][2]), "+r"(acc[i][2 * jp][3])
                    : "r"(a[i][0]), "r"(a[i][1]), "r"(a[i][2]), "r"(a[i][3]),
                      "r"(rb[0]), "r"(rb[1]));
                asm volatile(
                    "mma.sync.aligned.m16n8k32.row.col.s32.s8.s8.s32 "
                    "{%0,%1,%2,%3}, {%4,%5,%6,%7}, {%8,%9}, {%0,%1,%2,%3};\n"
                    : "+r"(acc[i][2 * jp + 1][0]), "+r"(acc[i][2 * jp + 1][1]),
                      "+r"(acc[i][2 * jp + 1][2]), "+r"(acc[i][2 * jp + 1][3])
                    : "r"(a[i][0]), "r"(a[i][1]), "r"(a[i][2]), "r"(a[i][3]),
                      "r"(rb[2]), "r"(rb[3]));
            }
        }
    }

    // ---- epilogue: relu+store int16, integer stats for next-layer LN ----
    const int qrow = lane >> 2, tig = lane & 3;

#pragma unroll
    for (int i = 0; i < 2; ++i) {
#pragma unroll
        for (int hi = 0; hi < 2; ++hi) {
            int lr = wm * 32 + i * 16 + hi * 8 + qrow;
            int grow = row0 + lr;
            if (!LAST) {
                int is1 = 0, imx = 0, imn = 0x7fffffff;
                float s2 = 0.f;
#pragma unroll
                for (int j = 0; j < 8; ++j) {
                    int q0 = max(acc[i][j][hi * 2], 0);       // exact int <= 32512
                    int q1 = max(acc[i][j][hi * 2 + 1], 0);
                    is1 += q0 + q1;
                    float f0 = (float)q0, f1 = (float)q1;
                    s2 = fmaf(f0, f0, s2);
                    s2 = fmaf(f1, f1, s2);
                    imx = max(imx, max(q0, q1));
                    imn = min(imn, min(q0, q1));
                    int col = wn * 64 + j * 8 + tig * 2;
                    *(unsigned*)(outs + (size_t)grow * DD + col) =
                        (unsigned)(q0 & 0xFFFF) | ((unsigned)q1 << 16);
                }
                is1 += __shfl_xor_sync(0xffffffffu, is1, 1);
                is1 += __shfl_xor_sync(0xffffffffu, is1, 2);
                s2  += __shfl_xor_sync(0xffffffffu, s2, 1);
                s2  += __shfl_xor_sync(0xffffffffu, s2, 2);
                imx  = max(imx, __shfl_xor_sync(0xffffffffu, imx, 1));
                imx  = max(imx, __shfl_xor_sync(0xffffffffu, imx, 2));
                imn  = min(imn, __shfl_xor_sync(0xffffffffu, imn, 1));
                imn  = min(imn, __shfl_xor_sync(0xffffffffu, imn, 2));
                if (tig == 0) {
                    risum[wn * 64 + lr] = is1;
                    rsq  [wn * 64 + lr] = s2;
                    rivx [wn * 64 + lr] = imx;
                    rivn [wn * 64 + lr] = imn;
                }
            } else {
#pragma unroll
                for (int j = 0; j < 8; ++j) {
                    float v0 = (float)acc[i][j][hi * 2]     * oscale;
                    float v1 = (float)acc[i][j][hi * 2 + 1] * oscale;
                    int col = wn * 64 + j * 8 + tig * 2;
                    *(float2*)(fout + (size_t)grow * DD + col) = make_float2(v0, v1);
                }
            }
        }
    }

    if constexpr (!LAST) {
        __syncthreads();
        if (tid < 64) {
            int a1i = (risum[tid] + risum[64 + tid]) + (risum[128 + tid] + risum[192 + tid]);
            float a2 = (rsq[tid] + rsq[64 + tid]) + (rsq[128 + tid] + rsq[192 + tid]);
            int mxi = max(max(rivx[tid], rivx[64 + tid]), max(rivx[128 + tid], rivx[192 + tid]));
            int mni = min(min(rivn[tid], rivn[64 + tid]), min(rivn[128 + tid], rivn[192 + tid]));
            float mu  = (float)a1i * oscale * (1.0f / 256.0f);
            float var = fmaxf(a2 * (oscale * oscale) * (1.0f / 256.0f) - mu * mu, 0.0f);
            float rsd = 1.0f / sqrtf(var + 1e-5f);
            g_mu[L + 1][row0 + tid]   = mu;
            g_rstd[L + 1][row0 + tid] = rsd;
            float mx = (float)mxi * oscale, mn = (float)mni * oscale;
            unsigned gu = __float_as_uint(fmaxf(mx - mu, mu - mn) * rsd);
#pragma unroll
            for (int o = 16; o; o >>= 1) gu = max(gu, __shfl_xor_sync(0xffffffffu, gu, o));
            if ((tid & 31) == 0) atomicMax(&g_gamma[L + 1], gu);   // direct global: no extra sync
        }
    }
}

// ---------------- launch ----------------
extern "C" void kernel_launch(void* const* d_in, const int* in_sizes, int n_in,
                              void* d_out, int out_size) {
    const float* x  = (const float*)d_in[0];
    const float* W1 = (const float*)d_in[1];
    const float* W2 = (const float*)d_in[2];
    const float* W3 = (const float*)d_in[3];
    float* out = (float*)d_out;

    constexpr int SMEM = 20736 + 65536;  // 86272 B
    cudaFuncSetAttribute(layer_kernel<0>, cudaFuncAttributeMaxDynamicSharedMemorySize, SMEM);
    cudaFuncSetAttribute(layer_kernel<1>, cudaFuncAttributeMaxDynamicSharedMemorySize, SMEM);
    cudaFuncSetAttribute(layer_kernel<2>, cudaFuncAttributeMaxDynamicSharedMemorySize, SMEM);

    wprep_kernel<<<3, 1024>>>(W1, W2, W3);
    stats_kernel<<<BN / 16, 256>>>(x);
    layer_kernel<0><<<NBLK, 256, SMEM>>>(x, nullptr);
    layer_kernel<1><<<NBLK, 256, SMEM>>>(nullptr, nullptr);
    layer_kernel<2><<<NBLK, 256, SMEM>>>(nullptr, out);
}